// round 1
// baseline (speedup 1.0000x reference)
#include <cuda_runtime.h>

// Problem constants (fixed by the dataset)
#define B_DIM   2048
#define IN_DIM  1024
#define H_DIM   2048
#define OUT_DIM 1024
#define BS      32
#define RB      (H_DIM / BS)   // 64 row blocks

// Intermediate activations (device globals: no allocation allowed)
__device__ float g_h1[(size_t)B_DIM * H_DIM];
__device__ float g_h2[(size_t)B_DIM * H_DIM];

// ---------------------------------------------------------------------------
// GEMM (NT): C[M,N] = act(A[M,K] @ B[N,K]^T + bias[N])
// Block tile 128x128, K-step 8, 256 threads, 8x8 register tile per thread.
// ---------------------------------------------------------------------------
template <bool RELU>
__global__ __launch_bounds__(256) void gemm_nt_kernel(
    const float* __restrict__ A, const float* __restrict__ Bm,
    const float* __restrict__ bias, float* __restrict__ C,
    int M, int N, int K)
{
    __shared__ float As[8][128];
    __shared__ float Bs[8][128];

    const int tid  = threadIdx.x;
    const int brow = blockIdx.y * 128;
    const int bcol = blockIdx.x * 128;

    // Global->shared loading indices: each thread loads one float4 of A and B
    // per K-step (128 rows x 8 cols per tile).
    const int lrow = tid >> 1;          // 0..127
    const int lc4  = (tid & 1) * 4;     // 0 or 4

    // Compute thread mapping: 16x16 threads, each 8x8 outputs.
    const int ty = tid >> 4;            // 0..15 (rows)
    const int tx = tid & 15;            // 0..15 (cols)

    float acc[8][8];
#pragma unroll
    for (int i = 0; i < 8; i++)
#pragma unroll
        for (int j = 0; j < 8; j++) acc[i][j] = 0.0f;

    const float* Aptr = A  + (size_t)(brow + lrow) * K + lc4;
    const float* Bptr = Bm + (size_t)(bcol + lrow) * K + lc4;

    for (int k0 = 0; k0 < K; k0 += 8) {
        float4 a4 = *(const float4*)(Aptr + k0);
        float4 b4 = *(const float4*)(Bptr + k0);
        As[lc4 + 0][lrow] = a4.x;
        As[lc4 + 1][lrow] = a4.y;
        As[lc4 + 2][lrow] = a4.z;
        As[lc4 + 3][lrow] = a4.w;
        Bs[lc4 + 0][lrow] = b4.x;
        Bs[lc4 + 1][lrow] = b4.y;
        Bs[lc4 + 2][lrow] = b4.z;
        Bs[lc4 + 3][lrow] = b4.w;
        __syncthreads();

#pragma unroll
        for (int k = 0; k < 8; k++) {
            float4 a0 = *(const float4*)&As[k][ty * 8];
            float4 a1 = *(const float4*)&As[k][ty * 8 + 4];
            float4 b0 = *(const float4*)&Bs[k][tx * 8];
            float4 b1 = *(const float4*)&Bs[k][tx * 8 + 4];
            float ar[8] = {a0.x, a0.y, a0.z, a0.w, a1.x, a1.y, a1.z, a1.w};
            float br[8] = {b0.x, b0.y, b0.z, b0.w, b1.x, b1.y, b1.z, b1.w};
#pragma unroll
            for (int i = 0; i < 8; i++)
#pragma unroll
                for (int j = 0; j < 8; j++)
                    acc[i][j] = fmaf(ar[i], br[j], acc[i][j]);
        }
        __syncthreads();
    }

    // Epilogue: bias + optional relu, float4 stores.
    float bv[8];
#pragma unroll
    for (int j = 0; j < 8; j++) bv[j] = bias[bcol + tx * 8 + j];

#pragma unroll
    for (int i = 0; i < 8; i++) {
        const int row = brow + ty * 8 + i;
        float o[8];
#pragma unroll
        for (int j = 0; j < 8; j++) {
            float v = acc[i][j] + bv[j];
            if (RELU) v = fmaxf(v, 0.0f);
            o[j] = v;
        }
        float4* dst = (float4*)(C + (size_t)row * N + bcol + tx * 8);
        dst[0] = make_float4(o[0], o[1], o[2], o[3]);
        dst[1] = make_float4(o[4], o[5], o[6], o[7]);
    }
}

// ---------------------------------------------------------------------------
// BSR layer: h2[b, rb*32+i] = relu( sum_{p in row rb} sum_j
//                h1[b, col[p]*32+j] * vals[p][i][j]  + b2[rb*32+i] )
// Grid: (batch tiles of 128) x (64 row blocks). 128 threads.
// Thread tile: 8 (batch) x 4 (i).
// ---------------------------------------------------------------------------
__global__ __launch_bounds__(128) void bsr_kernel(
    const float* __restrict__ h1, const int* __restrict__ crow,
    const int* __restrict__ cols, const float* __restrict__ vals,
    const float* __restrict__ bias, float* __restrict__ h2)
{
    __shared__ float Hs[128][33];  // [batch][j], padded
    __shared__ float Vs[32][33];   // [i][j], padded

    const int tid = threadIdx.x;
    const int rb  = blockIdx.y;
    const int b0  = blockIdx.x * 128;

    const int ty = tid >> 3;   // 0..15 -> batch group of 8
    const int tx = tid & 7;    // 0..7  -> i group of 4

    float acc[8][4];
#pragma unroll
    for (int b = 0; b < 8; b++)
#pragma unroll
        for (int i = 0; i < 4; i++) acc[b][i] = 0.0f;

    const int s = crow[rb];
    const int e = crow[rb + 1];

    for (int p = s; p < e; p++) {
        const int cb = cols[p];

        // Load 128x32 gathered slice of h1 (1024 float4, 8 per thread).
        const float* hsrc = h1 + (size_t)b0 * H_DIM + cb * BS;
#pragma unroll
        for (int t = 0; t < 8; t++) {
            const int idx = tid + t * 128;        // float4 index 0..1023
            const int row = idx >> 3;
            const int c4  = (idx & 7) << 2;
            float4 v = *(const float4*)(hsrc + (size_t)row * H_DIM + c4);
            Hs[row][c4 + 0] = v.x;
            Hs[row][c4 + 1] = v.y;
            Hs[row][c4 + 2] = v.z;
            Hs[row][c4 + 3] = v.w;
        }
        // Load 32x32 value block (256 float4, 2 per thread).
        const float* vsrc = vals + (size_t)p * (BS * BS);
#pragma unroll
        for (int t = 0; t < 2; t++) {
            const int idx = tid + t * 128;        // float4 index 0..255
            const int i  = idx >> 3;
            const int c4 = (idx & 7) << 2;
            float4 v = *(const float4*)(vsrc + i * BS + c4);
            Vs[i][c4 + 0] = v.x;
            Vs[i][c4 + 1] = v.y;
            Vs[i][c4 + 2] = v.z;
            Vs[i][c4 + 3] = v.w;
        }
        __syncthreads();

#pragma unroll
        for (int j = 0; j < 32; j++) {
            float hv[8], vv[4];
#pragma unroll
            for (int b = 0; b < 8; b++) hv[b] = Hs[ty * 8 + b][j];
#pragma unroll
            for (int i = 0; i < 4; i++) vv[i] = Vs[tx * 4 + i][j];
#pragma unroll
            for (int b = 0; b < 8; b++)
#pragma unroll
                for (int i = 0; i < 4; i++)
                    acc[b][i] = fmaf(hv[b], vv[i], acc[b][i]);
        }
        __syncthreads();
    }

    // Epilogue: bias + relu, float4 store per batch row.
    const int ib = rb * BS + tx * 4;
    float bv[4];
#pragma unroll
    for (int i = 0; i < 4; i++) bv[i] = bias[ib + i];

#pragma unroll
    for (int b = 0; b < 8; b++) {
        const int row = b0 + ty * 8 + b;
        float o[4];
#pragma unroll
        for (int i = 0; i < 4; i++) o[i] = fmaxf(acc[b][i] + bv[i], 0.0f);
        *(float4*)(h2 + (size_t)row * H_DIM + ib) = make_float4(o[0], o[1], o[2], o[3]);
    }
}

// ---------------------------------------------------------------------------
// Launcher: 3 sequential kernels on the default stream (graph-capturable).
// ---------------------------------------------------------------------------
extern "C" void kernel_launch(void* const* d_in, const int* in_sizes, int n_in,
                              void* d_out, int out_size)
{
    const float* x    = (const float*)d_in[0];
    const float* W1   = (const float*)d_in[1];
    const float* b1   = (const float*)d_in[2];
    const int*   crow = (const int*)d_in[3];
    const int*   cols = (const int*)d_in[4];
    const float* vals = (const float*)d_in[5];
    const float* b2   = (const float*)d_in[6];
    const float* W3   = (const float*)d_in[7];
    const float* b3   = (const float*)d_in[8];
    float* out = (float*)d_out;

    float *h1, *h2;
    cudaGetSymbolAddress((void**)&h1, g_h1);
    cudaGetSymbolAddress((void**)&h2, g_h2);

    // Layer 1: h1 = relu(x @ W1^T + b1)   [2048 x 2048]
    gemm_nt_kernel<true><<<dim3(H_DIM / 128, B_DIM / 128), 256>>>(
        x, W1, b1, h1, B_DIM, H_DIM, IN_DIM);

    // Layer 2: h2 = relu(BSR(h1) + b2)    [2048 x 2048]
    bsr_kernel<<<dim3(B_DIM / 128, RB), 128>>>(h1, crow, cols, vals, b2, h2);

    // Layer 3: out = h2 @ W3^T + b3       [2048 x 1024]
    gemm_nt_kernel<false><<<dim3(OUT_DIM / 128, B_DIM / 128), 256>>>(
        h2, W3, b3, out, B_DIM, OUT_DIM, H_DIM);
}

// round 3
// speedup vs baseline: 2.5360x; 2.5360x over previous
#include <cuda_runtime.h>
#include <cuda_bf16.h>
#include <cstdint>

// Problem constants (fixed by dataset)
#define B_DIM   2048
#define IN_DIM  1024
#define H_DIM   2048
#define OUT_DIM 1024
#define BS      32
#define RB      64

#define KW 20            // padded word stride (16 data words + 4 pad) -> conflict-free
#define A_TILE_W (128 * KW)   // 2560 words
#define B_TILE_W_D (128 * KW) // dense B tile
#define B_TILE_W_S (32 * KW)  // bsr B tile (640 words)

// Intermediates (device globals: no allocation allowed)
__device__ float g_h1[(size_t)B_DIM * H_DIM];
__device__ float g_h2[(size_t)B_DIM * H_DIM];

// ---------------------------------------------------------------------------
// Helpers
// ---------------------------------------------------------------------------
__device__ __forceinline__ void mma_bf16(float c[4], const uint32_t a[4],
                                         const uint32_t b[2]) {
    asm volatile(
        "mma.sync.aligned.m16n8k16.row.col.f32.bf16.bf16.f32 "
        "{%0,%1,%2,%3}, {%4,%5,%6,%7}, {%8,%9}, {%0,%1,%2,%3};"
        : "+f"(c[0]), "+f"(c[1]), "+f"(c[2]), "+f"(c[3])
        : "r"(a[0]), "r"(a[1]), "r"(a[2]), "r"(a[3]), "r"(b[0]), "r"(b[1]));
}

// Split float4 into packed-bf16x2 hi (2 words) + lo (2 words), store to smem.
__device__ __forceinline__ void split_sts(uint32_t* hi, uint32_t* lo, float4 v) {
    __nv_bfloat162 h0 = __floats2bfloat162_rn(v.x, v.y);
    __nv_bfloat162 h1 = __floats2bfloat162_rn(v.z, v.w);
    float2 f0 = __bfloat1622float2(h0);
    float2 f1 = __bfloat1622float2(h1);
    __nv_bfloat162 l0 = __floats2bfloat162_rn(v.x - f0.x, v.y - f0.y);
    __nv_bfloat162 l1 = __floats2bfloat162_rn(v.z - f1.x, v.w - f1.y);
    uint2 hw; hw.x = *(uint32_t*)&h0; hw.y = *(uint32_t*)&h1;
    uint2 lw; lw.x = *(uint32_t*)&l0; lw.y = *(uint32_t*)&l1;
    *(uint2*)hi = hw;
    *(uint2*)lo = lw;
}

// ---------------------------------------------------------------------------
// Dense GEMM (NT): C[M,N] = act(A[M,K] @ B[N,K]^T + bias)
// CTA 128x128, 8 warps (64x32 warp tiles), K-chunk 32, bf16 3-pass split,
// double-buffered smem with LDG prefetch.
// smem: 2 bufs x (Ahi,Alo,Bhi,Blo) x 2560 words = 81920 bytes.
// ---------------------------------------------------------------------------
#define D_STAGE_W (4 * A_TILE_W)  // 10240 words per buffer

template <bool RELU>
__global__ __launch_bounds__(256, 1) void gemm_mma_kernel(
    const float* __restrict__ A, const float* __restrict__ Bm,
    const float* __restrict__ bias, float* __restrict__ C, int N, int K)
{
    extern __shared__ uint32_t sm[];
    const int tid  = threadIdx.x;
    const int lane = tid & 31;
    const int wid  = tid >> 5;
    const int brow = blockIdx.y * 128;
    const int bcol = blockIdx.x * 128;
    const int wm = (wid >> 2) * 64;   // warp row origin in tile
    const int wn = (wid & 3) * 32;    // warp col origin in tile

    // gmem load mapping: idx = tid + t*256 -> row = idx>>3, c4 = idx&7
    const int lrow = tid >> 3;  // base row for t=0 pattern recomputed per t

    float acc[4][4][4];
#pragma unroll
    for (int i = 0; i < 4; i++)
#pragma unroll
        for (int j = 0; j < 4; j++)
#pragma unroll
            for (int r = 0; r < 4; r++) acc[i][j][r] = 0.0f;

    const int chunks = K / 32;
    float4 pA[4], pB[4];

    // prologue: load chunk 0
#pragma unroll
    for (int t = 0; t < 4; t++) {
        const int idx = tid + t * 256;
        const int row = idx >> 3, c4 = idx & 7;
        pA[t] = *(const float4*)(A  + (size_t)(brow + row) * K + c4 * 4);
        pB[t] = *(const float4*)(Bm + (size_t)(bcol + row) * K + c4 * 4);
    }
#pragma unroll
    for (int t = 0; t < 4; t++) {
        const int idx = tid + t * 256;
        const int row = idx >> 3, c4 = idx & 7;
        const int off = row * KW + c4 * 2;
        split_sts(sm + off,                 sm + A_TILE_W + off,     pA[t]);
        split_sts(sm + 2 * A_TILE_W + off,  sm + 3 * A_TILE_W + off, pB[t]);
    }
    __syncthreads();

    for (int kc = 0; kc < chunks; kc++) {
        const int buf = kc & 1;
        const bool more = (kc + 1) < chunks;

        // prefetch next chunk
        if (more) {
            const int k0 = (kc + 1) * 32;
#pragma unroll
            for (int t = 0; t < 4; t++) {
                const int idx = tid + t * 256;
                const int row = idx >> 3, c4 = idx & 7;
                pA[t] = *(const float4*)(A  + (size_t)(brow + row) * K + k0 + c4 * 4);
                pB[t] = *(const float4*)(Bm + (size_t)(bcol + row) * K + k0 + c4 * 4);
            }
        }

        // compute current buffer
        const uint32_t* sAh = sm + buf * D_STAGE_W;
        const uint32_t* sAl = sAh + A_TILE_W;
        const uint32_t* sBh = sAh + 2 * A_TILE_W;
        const uint32_t* sBl = sAh + 3 * A_TILE_W;
#pragma unroll
        for (int ks = 0; ks < 2; ks++) {
            const int kw = ks * 8 + (lane & 3);
            uint32_t ah[4][4], al[4][4], bh[4][2], bl[4][2];
#pragma unroll
            for (int i = 0; i < 4; i++) {
                const int r = wm + i * 16 + (lane >> 2);
                ah[i][0] = sAh[r * KW + kw];
                ah[i][1] = sAh[(r + 8) * KW + kw];
                ah[i][2] = sAh[r * KW + kw + 4];
                ah[i][3] = sAh[(r + 8) * KW + kw + 4];
                al[i][0] = sAl[r * KW + kw];
                al[i][1] = sAl[(r + 8) * KW + kw];
                al[i][2] = sAl[r * KW + kw + 4];
                al[i][3] = sAl[(r + 8) * KW + kw + 4];
            }
#pragma unroll
            for (int j = 0; j < 4; j++) {
                const int n = wn + j * 8 + (lane >> 2);
                bh[j][0] = sBh[n * KW + kw];
                bh[j][1] = sBh[n * KW + kw + 4];
                bl[j][0] = sBl[n * KW + kw];
                bl[j][1] = sBl[n * KW + kw + 4];
            }
#pragma unroll
            for (int i = 0; i < 4; i++)
#pragma unroll
                for (int j = 0; j < 4; j++) {
                    mma_bf16(acc[i][j], ah[i], bh[j]);
                    mma_bf16(acc[i][j], ah[i], bl[j]);
                    mma_bf16(acc[i][j], al[i], bh[j]);
                }
        }

        // store next chunk into the other buffer
        if (more) {
            uint32_t* dst = sm + (buf ^ 1) * D_STAGE_W;
#pragma unroll
            for (int t = 0; t < 4; t++) {
                const int idx = tid + t * 256;
                const int row = idx >> 3, c4 = idx & 7;
                const int off = row * KW + c4 * 2;
                split_sts(dst + off,                dst + A_TILE_W + off,     pA[t]);
                split_sts(dst + 2 * A_TILE_W + off, dst + 3 * A_TILE_W + off, pB[t]);
            }
        }
        __syncthreads();
    }

    // epilogue
#pragma unroll
    for (int i = 0; i < 4; i++) {
        const int r0 = brow + wm + i * 16 + (lane >> 2);
#pragma unroll
        for (int j = 0; j < 4; j++) {
            const int c0 = bcol + wn + j * 8 + 2 * (lane & 3);
            const float bx = __ldg(&bias[c0]), by = __ldg(&bias[c0 + 1]);
            float2 v0, v1;
            v0.x = acc[i][j][0] + bx; v0.y = acc[i][j][1] + by;
            v1.x = acc[i][j][2] + bx; v1.y = acc[i][j][3] + by;
            if (RELU) {
                v0.x = fmaxf(v0.x, 0.f); v0.y = fmaxf(v0.y, 0.f);
                v1.x = fmaxf(v1.x, 0.f); v1.y = fmaxf(v1.y, 0.f);
            }
            *(float2*)(C + (size_t)r0 * N + c0)       = v0;
            *(float2*)(C + (size_t)(r0 + 8) * N + c0) = v1;
        }
    }
    (void)lrow;
}

// ---------------------------------------------------------------------------
// BSR layer: per (batch-tile 128, row-block rb):
//   C[128x32] = sum_p h1[b0:b0+128, col_p*32:+32] @ vals[p]^T, K-chunk = block.
// 8 warps (32x16 warp tiles). smem: 2 bufs x (Ahi,Alo 2560w; Bhi,Blo 640w).
// ---------------------------------------------------------------------------
#define S_STAGE_W (2 * A_TILE_W + 2 * B_TILE_W_S)  // 6400 words per buffer

__global__ __launch_bounds__(256, 1) void bsr_mma_kernel(
    const float* __restrict__ h1, const int* __restrict__ crow,
    const int* __restrict__ cols, const float* __restrict__ vals,
    const float* __restrict__ bias, float* __restrict__ h2)
{
    extern __shared__ uint32_t sm[];
    const int tid  = threadIdx.x;
    const int lane = tid & 31;
    const int wid  = tid >> 5;
    const int b0 = blockIdx.x * 128;
    const int rb = blockIdx.y;
    const int wm = (wid >> 1) * 32;  // 4 warp rows
    const int wn = (wid & 1) * 16;   // 2 warp cols

    float acc[2][2][4];
#pragma unroll
    for (int i = 0; i < 2; i++)
#pragma unroll
        for (int j = 0; j < 2; j++)
#pragma unroll
            for (int r = 0; r < 4; r++) acc[i][j][r] = 0.0f;

    const int s0 = __ldg(&crow[rb]);
    const int chunks = __ldg(&crow[rb + 1]) - s0;

    float4 pA[4], pB;

    // prologue: chunk 0
    {
        const int cb = __ldg(&cols[s0]);
        const float* asrc = h1 + (size_t)b0 * H_DIM + cb * 32;
#pragma unroll
        for (int t = 0; t < 4; t++) {
            const int idx = tid + t * 256;
            const int row = idx >> 3, c4 = idx & 7;
            pA[t] = *(const float4*)(asrc + (size_t)row * H_DIM + c4 * 4);
        }
        pB = *(const float4*)(vals + (size_t)s0 * (BS * BS) + (tid >> 3) * BS + (tid & 7) * 4);
    }
    {
#pragma unroll
        for (int t = 0; t < 4; t++) {
            const int idx = tid + t * 256;
            const int row = idx >> 3, c4 = idx & 7;
            const int off = row * KW + c4 * 2;
            split_sts(sm + off, sm + A_TILE_W + off, pA[t]);
        }
        const int off = (tid >> 3) * KW + (tid & 7) * 2;
        split_sts(sm + 2 * A_TILE_W + off, sm + 2 * A_TILE_W + B_TILE_W_S + off, pB);
    }
    __syncthreads();

    for (int kc = 0; kc < chunks; kc++) {
        const int buf = kc & 1;
        const bool more = (kc + 1) < chunks;

        if (more) {
            const int p = s0 + kc + 1;
            const int cb = __ldg(&cols[p]);
            const float* asrc = h1 + (size_t)b0 * H_DIM + cb * 32;
#pragma unroll
            for (int t = 0; t < 4; t++) {
                const int idx = tid + t * 256;
                const int row = idx >> 3, c4 = idx & 7;
                pA[t] = *(const float4*)(asrc + (size_t)row * H_DIM + c4 * 4);
            }
            pB = *(const float4*)(vals + (size_t)p * (BS * BS) + (tid >> 3) * BS + (tid & 7) * 4);
        }

        const uint32_t* sAh = sm + buf * S_STAGE_W;
        const uint32_t* sAl = sAh + A_TILE_W;
        const uint32_t* sBh = sAh + 2 * A_TILE_W;
        const uint32_t* sBl = sBh + B_TILE_W_S;
#pragma unroll
        for (int ks = 0; ks < 2; ks++) {
            const int kw = ks * 8 + (lane & 3);
            uint32_t ah[2][4], al[2][4], bh[2][2], bl[2][2];
#pragma unroll
            for (int i = 0; i < 2; i++) {
                const int r = wm + i * 16 + (lane >> 2);
                ah[i][0] = sAh[r * KW + kw];
                ah[i][1] = sAh[(r + 8) * KW + kw];
                ah[i][2] = sAh[r * KW + kw + 4];
                ah[i][3] = sAh[(r + 8) * KW + kw + 4];
                al[i][0] = sAl[r * KW + kw];
                al[i][1] = sAl[(r + 8) * KW + kw];
                al[i][2] = sAl[r * KW + kw + 4];
                al[i][3] = sAl[(r + 8) * KW + kw + 4];
            }
#pragma unroll
            for (int j = 0; j < 2; j++) {
                const int n = wn + j * 8 + (lane >> 2);
                bh[j][0] = sBh[n * KW + kw];
                bh[j][1] = sBh[n * KW + kw + 4];
                bl[j][0] = sBl[n * KW + kw];
                bl[j][1] = sBl[n * KW + kw + 4];
            }
#pragma unroll
            for (int i = 0; i < 2; i++)
#pragma unroll
                for (int j = 0; j < 2; j++) {
                    mma_bf16(acc[i][j], ah[i], bh[j]);
                    mma_bf16(acc[i][j], ah[i], bl[j]);
                    mma_bf16(acc[i][j], al[i], bh[j]);
                }
        }

        if (more) {
            uint32_t* dst = sm + (buf ^ 1) * S_STAGE_W;
#pragma unroll
            for (int t = 0; t < 4; t++) {
                const int idx = tid + t * 256;
                const int row = idx >> 3, c4 = idx & 7;
                const int off = row * KW + c4 * 2;
                split_sts(dst + off, dst + A_TILE_W + off, pA[t]);
            }
            const int off = (tid >> 3) * KW + (tid & 7) * 2;
            split_sts(dst + 2 * A_TILE_W + off, dst + 2 * A_TILE_W + B_TILE_W_S + off, pB);
        }
        __syncthreads();
    }

    // epilogue: bias + relu
#pragma unroll
    for (int i = 0; i < 2; i++) {
        const int r0 = b0 + wm + i * 16 + (lane >> 2);
#pragma unroll
        for (int j = 0; j < 2; j++) {
            const int c0 = rb * 32 + wn + j * 8 + 2 * (lane & 3);
            const float bx = __ldg(&bias[c0]), by = __ldg(&bias[c0 + 1]);
            float2 v0, v1;
            v0.x = fmaxf(acc[i][j][0] + bx, 0.f);
            v0.y = fmaxf(acc[i][j][1] + by, 0.f);
            v1.x = fmaxf(acc[i][j][2] + bx, 0.f);
            v1.y = fmaxf(acc[i][j][3] + by, 0.f);
            *(float2*)(h2 + (size_t)r0 * H_DIM + c0)       = v0;
            *(float2*)(h2 + (size_t)(r0 + 8) * H_DIM + c0) = v1;
        }
    }
}

// ---------------------------------------------------------------------------
// Launcher
// ---------------------------------------------------------------------------
#define D_SMEM_BYTES (2 * D_STAGE_W * 4)  // 81920
#define S_SMEM_BYTES (2 * S_STAGE_W * 4)  // 51200

extern "C" void kernel_launch(void* const* d_in, const int* in_sizes, int n_in,
                              void* d_out, int out_size)
{
    const float* x    = (const float*)d_in[0];
    const float* W1   = (const float*)d_in[1];
    const float* b1   = (const float*)d_in[2];
    const int*   crow = (const int*)d_in[3];
    const int*   cols = (const int*)d_in[4];
    const float* vals = (const float*)d_in[5];
    const float* b2   = (const float*)d_in[6];
    const float* W3   = (const float*)d_in[7];
    const float* b3   = (const float*)d_in[8];
    float* out = (float*)d_out;

    float *h1, *h2;
    cudaGetSymbolAddress((void**)&h1, g_h1);
    cudaGetSymbolAddress((void**)&h2, g_h2);

    cudaFuncSetAttribute(gemm_mma_kernel<true>,
                         cudaFuncAttributeMaxDynamicSharedMemorySize, D_SMEM_BYTES);
    cudaFuncSetAttribute(gemm_mma_kernel<false>,
                         cudaFuncAttributeMaxDynamicSharedMemorySize, D_SMEM_BYTES);
    cudaFuncSetAttribute(bsr_mma_kernel,
                         cudaFuncAttributeMaxDynamicSharedMemorySize, S_SMEM_BYTES);

    // Layer 1: h1 = relu(x @ W1^T + b1)
    gemm_mma_kernel<true><<<dim3(H_DIM / 128, B_DIM / 128), 256, D_SMEM_BYTES>>>(
        x, W1, b1, h1, H_DIM, IN_DIM);

    // Layer 2: h2 = relu(BSR(h1) + b2)
    bsr_mma_kernel<<<dim3(B_DIM / 128, RB), 256, S_SMEM_BYTES>>>(
        h1, crow, cols, vals, b2, h2);

    // Layer 3: out = h2 @ W3^T + b3
    gemm_mma_kernel<false><<<dim3(OUT_DIM / 128, B_DIM / 128), 256, D_SMEM_BYTES>>>(
        h2, W3, b3, out, OUT_DIM, H_DIM);
}